// round 2
// baseline (speedup 1.0000x reference)
#include <cuda_runtime.h>

// Problem constants (fixed by the reference)
#define NIN   4096
#define NOUT  1024
#define BC    128        // B * C_IN = 4 * 32
#define B_DIM 4
#define C_DIM 32
#define MAXB  768        // per-output-row bin capacity (mean 390, sigma ~20)

// Scratch (device globals; no allocation allowed)
__device__ float4 g_gft4[NIN * (BC / 4)];     // 2 MB  : (G @ F) transposed to (n, b*32+oc)
__device__ int    g_bin[NOUT * MAXB];         // 3 MB  : edge bins (stores idx_in)
__device__ int    g_cnt[NOUT];                // bin counters

// ---------------------------------------------------------------------------
// Kernel A: fused channel-GEMM + transpose.
//   gft[n, b*32+oc] = sum_i G[oc,i] * F[b,i,n]
// Block = 256 threads handles one b and a 64-wide n tile (grid = 4*64 = 256).
// Reads coalesced along n into smem; writes coalesced along oc.
// Also zeroes the bin counters.
// ---------------------------------------------------------------------------
__global__ void qc_transform(const float* __restrict__ F,
                             const float* __restrict__ G) {
    __shared__ float Fs[C_DIM * 65];   // Fs[i*65 + n_local], pad avoids conflicts
    __shared__ float Gs[C_DIM * 33];   // Gs[oc*33 + i]

    int t    = threadIdx.x;
    int blk  = blockIdx.x;
    int b    = blk >> 6;          // 0..3
    int n0   = (blk & 63) * 64;   // tile start

    if (blk == 0) {
        for (int k = t; k < NOUT; k += 256) g_cnt[k] = 0;
    }

    // Stage F tile: 32 i-rows x 64 n-cols, coalesced along n
    #pragma unroll
    for (int k = 0; k < 8; k++) {
        int idx = t + k * 256;            // 0..2047
        int i   = idx >> 6;
        int n   = idx & 63;
        Fs[i * 65 + n] = F[b * (C_DIM * NIN) + i * NIN + n0 + n];
    }
    // Stage G transposed-access layout
    #pragma unroll
    for (int k = 0; k < 4; k++) {
        int idx = t + k * 256;            // 0..1023
        int oc  = idx >> 5;
        int i   = idx & 31;
        Gs[oc * 33 + i] = G[idx];
    }
    __syncthreads();

    float* gft = reinterpret_cast<float*>(g_gft4);
    int oc   = t & 31;           // lane = output channel
    int wid  = t >> 5;           // 8 warps

    #pragma unroll
    for (int r = 0; r < 8; r++) {
        int nl = r * 8 + wid;    // local n
        float sum = 0.0f;
        #pragma unroll
        for (int i = 0; i < C_DIM; i++)
            sum = fmaf(Gs[oc * 33 + i], Fs[i * 65 + nl], sum);
        // warp writes 32 consecutive floats -> 128B coalesced store
        gft[(n0 + nl) * BC + b * C_DIM + oc] = sum;
    }
}

// ---------------------------------------------------------------------------
// Kernel B: bin edges by idx_out. Thread per edge.
// ---------------------------------------------------------------------------
__global__ void qc_bin(const int* __restrict__ idx_out,
                       const int* __restrict__ idx_in,
                       int E) {
    int e = blockIdx.x * blockDim.x + threadIdx.x;
    if (e >= E) return;
    int io  = idx_out[e];
    int pos = atomicAdd(&g_cnt[io], 1);
    if (pos < MAXB) g_bin[io * MAXB + pos] = idx_in[e];
}

// ---------------------------------------------------------------------------
// Kernel C: per-output-row gather-accumulate, writes final output.
// Block = 256 threads handles 2 output rows; 4 warps per row, each warp
// strides over the row's edge list accumulating float4 in registers.
// out[b, oc, o] = acc[o, b*32+oc]  (G already folded in)
// ---------------------------------------------------------------------------
__global__ void qc_accum(float* __restrict__ out) {
    __shared__ float4 part[8][32];

    int t    = threadIdx.x;
    int warp = t >> 5;
    int lane = t & 31;
    int r    = warp >> 2;        // row within block (0/1)
    int wr   = warp & 3;         // warp within row (0..3)
    int o    = blockIdx.x * 2 + r;

    int cnt = g_cnt[o];
    if (cnt > MAXB) cnt = MAXB;  // statistically unreachable guard
    const int* bins = g_bin + o * MAXB;

    float4 acc = make_float4(0.f, 0.f, 0.f, 0.f);

    int j = wr;
    // 4-way unrolled (stride 16 across the 4 warps) for memory-level parallelism
    for (; j + 12 < cnt; j += 16) {
        int i0 = bins[j];
        int i1 = bins[j + 4];
        int i2 = bins[j + 8];
        int i3 = bins[j + 12];
        float4 v0 = g_gft4[i0 * (BC / 4) + lane];
        float4 v1 = g_gft4[i1 * (BC / 4) + lane];
        float4 v2 = g_gft4[i2 * (BC / 4) + lane];
        float4 v3 = g_gft4[i3 * (BC / 4) + lane];
        acc.x += v0.x + v1.x + v2.x + v3.x;
        acc.y += v0.y + v1.y + v2.y + v3.y;
        acc.z += v0.z + v1.z + v2.z + v3.z;
        acc.w += v0.w + v1.w + v2.w + v3.w;
    }
    for (; j < cnt; j += 4) {
        float4 v = g_gft4[bins[j] * (BC / 4) + lane];
        acc.x += v.x; acc.y += v.y; acc.z += v.z; acc.w += v.w;
    }

    part[warp][lane] = acc;
    __syncthreads();

    if (warp < 2) {              // warp w finalizes row blockIdx.x*2 + w
        float4 a = part[warp * 4 + 0][lane];
        float4 b4 = part[warp * 4 + 1][lane];
        float4 c = part[warp * 4 + 2][lane];
        float4 d = part[warp * 4 + 3][lane];
        float s[4];
        s[0] = a.x + b4.x + c.x + d.x;
        s[1] = a.y + b4.y + c.y + d.y;
        s[2] = a.z + b4.z + c.z + d.z;
        s[3] = a.w + b4.w + c.w + d.w;
        int oo = blockIdx.x * 2 + warp;
        #pragma unroll
        for (int k = 0; k < 4; k++) {
            int c128 = 4 * lane + k;               // b*32 + oc
            int b_   = c128 >> 5;
            int oc   = c128 & 31;
            out[b_ * (C_DIM * NOUT) + oc * NOUT + oo] = s[k];
        }
    }
}

// ---------------------------------------------------------------------------
extern "C" void kernel_launch(void* const* d_in, const int* in_sizes, int n_in,
                              void* d_out, int out_size) {
    const float* features = (const float*)d_in[0];   // (4,32,4096) f32
    const float* G        = (const float*)d_in[1];   // (32,32)     f32
    const int*   idx_out  = (const int*)d_in[2];     // (E,) i32
    const int*   idx_in   = (const int*)d_in[3];     // (E,) i32
    float*       out      = (float*)d_out;           // (4,32,1024) f32
    int E = in_sizes[2];

    qc_transform<<<256, 256>>>(features, G);
    qc_bin<<<(E + 255) / 256, 256>>>(idx_out, idx_in, E);
    qc_accum<<<NOUT / 2, 256>>>(out);
}

// round 6
// speedup vs baseline: 1.2148x; 1.2148x over previous
#include <cuda_runtime.h>
#include <cuda_fp16.h>
#include <cstdint>

// ---------------- problem constants ----------------
#define NIN   4096
#define NOUT  1024
#define BC    128          // B*C = 4*32
#define C_DIM 32

// GEMM: D[o(1024), bc(128)] = sum_k M[o,k] * gftT[bc,k]
#define KSPLIT 16
#define KPB    (NIN / KSPLIT)   // 256
#define KC     64               // k per smem chunk
#define NCHUNK (KPB / KC)       // 4
#define MTILES (NOUT / 128)     // 8
#define ROWH   72               // smem row stride in halves (64 + 16B pad)

// ---------------- device scratch ----------------
__device__ float  g_Mf[NOUT * NIN];            // 16.8 MB count matrix (fp32)
__device__ __half g_ghi[BC * NIN];             // 1 MB  (G@F)^T hi (fp16)
__device__ __half g_glo[BC * NIN];             // 1 MB  (G@F)^T lo (fp16)
__device__ float  g_part[KSPLIT * NOUT * BC];  // 8 MB  K-split partials

__device__ __forceinline__ uint32_t smem_u32(const void* p) {
    uint32_t a;
    asm("{ .reg .u64 t; cvta.to.shared.u64 t, %1; cvt.u32.u64 %0, t; }" : "=r"(a) : "l"(p));
    return a;
}

__device__ __forceinline__ void ldsm_x4(uint32_t* r, uint32_t addr) {
    asm volatile("ldmatrix.sync.aligned.m8n8.x4.shared.b16 {%0,%1,%2,%3}, [%4];"
                 : "=r"(r[0]), "=r"(r[1]), "=r"(r[2]), "=r"(r[3]) : "r"(addr));
}

__device__ __forceinline__ void mma16816(float* c, const uint32_t* a,
                                         uint32_t b0, uint32_t b1) {
    asm volatile(
        "mma.sync.aligned.m16n8k16.row.col.f32.f16.f16.f32 "
        "{%0,%1,%2,%3}, {%4,%5,%6,%7}, {%8,%9}, {%0,%1,%2,%3};"
        : "+f"(c[0]), "+f"(c[1]), "+f"(c[2]), "+f"(c[3])
        : "r"(a[0]), "r"(a[1]), "r"(a[2]), "r"(a[3]), "r"(b0), "r"(b1));
}

// ---------------------------------------------------------------------------
// Kernel 1: zero M + fused channel-GEMM producing gftT hi/lo (fp16 split).
// gftT[b*32+oc][n] = sum_i G[oc,i]*F[b,i,n].  Grid = 64 (4 b x 16 n-tiles).
// ---------------------------------------------------------------------------
__global__ void qc_prep(const float* __restrict__ F, const float* __restrict__ G) {
    // zero count matrix: 1,048,576 float4 over 16384 threads
    float4* m4 = reinterpret_cast<float4*>(g_Mf);
    int gt = blockIdx.x * 256 + threadIdx.x;
    #pragma unroll
    for (int j = 0; j < 64; j++)
        m4[j * 16384 + gt] = make_float4(0.f, 0.f, 0.f, 0.f);

    __shared__ float Fs[C_DIM * 256];
    __shared__ float Gs[C_DIM * 33];
    int t  = threadIdx.x;
    int b  = blockIdx.x >> 4;
    int n0 = (blockIdx.x & 15) * 256;

    // Full F tile: 32*256 = 8192 entries -> 32 iterations (R4 bug was j<8).
    #pragma unroll
    for (int j = 0; j < 32; j++) {
        int idx = t + j * 256;                       // idx = i*256 + nl
        Fs[idx] = F[b * (C_DIM * NIN) + (idx >> 8) * NIN + n0 + (idx & 255)];
    }
    #pragma unroll
    for (int j = 0; j < 4; j++) {
        int idx = t + j * 256;
        Gs[(idx >> 5) * 33 + (idx & 31)] = G[idx];
    }
    __syncthreads();

    #pragma unroll 4
    for (int oc = 0; oc < 32; oc++) {
        float s = 0.f;
        #pragma unroll
        for (int i = 0; i < 32; i++)
            s = fmaf(Gs[oc * 33 + i], Fs[i * 256 + t], s);
        __half h = __float2half_rn(s);
        __half l = __float2half_rn(s - __half2float(h));
        int row = b * 32 + oc;
        g_ghi[row * NIN + n0 + t] = h;
        g_glo[row * NIN + n0 + t] = l;
    }
}

// ---------------------------------------------------------------------------
// Kernel 2: build count matrix. Thread per edge, spread fp32 atomics.
// ---------------------------------------------------------------------------
__global__ void qc_count(const int* __restrict__ idx_out,
                         const int* __restrict__ idx_in, int E) {
    int e = blockIdx.x * blockDim.x + threadIdx.x;
    if (e >= E) return;
    atomicAdd(&g_Mf[idx_out[e] * NIN + idx_in[e]], 1.0f);
}

// ---------------------------------------------------------------------------
// Kernel 3: HMMA GEMM. Block = 256 threads (8 warps, 4x2), D tile 128o x 128bc,
// K range KPB=256 in 4 chunks of 64. A = M (fp32->fp16 on load), B = hi & lo,
// both accumulating into the same f32 fragments.
// ---------------------------------------------------------------------------
__global__ void __launch_bounds__(256, 1) qc_gemm_mma() {
    extern __shared__ __half sm[];
    __half* As = sm;                 // 128 x ROWH
    __half* Bh = sm + 128 * ROWH;    // 128 x ROWH
    __half* Bl = sm + 256 * ROWH;    // 128 x ROWH

    int t    = threadIdx.x;
    int wid  = t >> 5;
    int lane = t & 31;
    int mt_b = blockIdx.x & 7;
    int ks   = blockIdx.x >> 3;
    int o0   = mt_b * 128;
    int k0   = ks * KPB;
    int wo   = (wid >> 1) * 32;      // warp o offset (0/32/64/96)
    int n0w  = (wid & 1) * 64;       // warp bc offset (0/64)

    uint32_t sA = smem_u32(As), sBh = smem_u32(Bh), sBl = smem_u32(Bl);

    float acc[2][8][4];
    #pragma unroll
    for (int i = 0; i < 2; i++)
        #pragma unroll
        for (int j = 0; j < 8; j++)
            #pragma unroll
            for (int q = 0; q < 4; q++) acc[i][j][q] = 0.f;

    for (int c = 0; c < NCHUNK; c++) {
        int kc0 = k0 + c * KC;

        // A tile: M[o0+row][kc0 + cp*2 ..] fp32 -> fp16 (coalesced 256B/warp)
        #pragma unroll
        for (int j = 0; j < 16; j++) {
            int idx = t + j * 256;          // 0..4095
            int row = idx >> 5, cp = idx & 31;
            float2 f2 = *reinterpret_cast<const float2*>(
                &g_Mf[(o0 + row) * NIN + kc0 + cp * 2]);
            *reinterpret_cast<__half2*>(&As[row * ROWH + cp * 2]) =
                __floats2half2_rn(f2.x, f2.y);
        }
        // B tiles hi/lo (uint32 = half2 moves, coalesced 128B/warp)
        #pragma unroll
        for (int j = 0; j < 16; j++) {
            int idx = t + j * 256;
            int row = idx >> 5, cp = idx & 31;
            int gsrc = row * NIN + kc0 + cp * 2;
            int sdst = row * ROWH + cp * 2;
            *reinterpret_cast<uint32_t*>(&Bh[sdst]) =
                *reinterpret_cast<const uint32_t*>(&g_ghi[gsrc]);
            *reinterpret_cast<uint32_t*>(&Bl[sdst]) =
                *reinterpret_cast<const uint32_t*>(&g_glo[gsrc]);
        }
        __syncthreads();

        #pragma unroll
        for (int kk = 0; kk < KC; kk += 16) {
            uint32_t a[2][4];
            #pragma unroll
            for (int mt = 0; mt < 2; mt++)
                ldsm_x4(a[mt], sA + 2 * ((wo + mt * 16 + (lane & 15)) * ROWH
                                          + kk + (lane >> 4) * 8));
            #pragma unroll
            for (int h = 0; h < 2; h++) {
                uint32_t sB = h ? sBl : sBh;
                #pragma unroll
                for (int ng = 0; ng < 4; ng++) {
                    uint32_t b[4];
                    ldsm_x4(b, sB + 2 * ((n0w + ng * 16 + (lane & 15)) * ROWH
                                          + kk + (lane >> 4) * 8));
                    #pragma unroll
                    for (int mt = 0; mt < 2; mt++) {
                        mma16816(acc[mt][ng * 2 + 0], a[mt], b[0], b[2]);
                        mma16816(acc[mt][ng * 2 + 1], a[mt], b[1], b[3]);
                    }
                }
            }
        }
        __syncthreads();
    }

    // Epilogue: write partials. c frag rows = lane>>2 (+8), cols = (lane&3)*2+{0,1}
    #pragma unroll
    for (int mt = 0; mt < 2; mt++) {
        #pragma unroll
        for (int nt = 0; nt < 8; nt++) {
            int o  = o0 + wo + mt * 16 + (lane >> 2);
            int bc = n0w + nt * 8 + (lane & 3) * 2;
            float* p = &g_part[(ks * NOUT + o) * BC + bc];
            *reinterpret_cast<float2*>(p) =
                make_float2(acc[mt][nt][0], acc[mt][nt][1]);
            *reinterpret_cast<float2*>(p + 8 * BC) =
                make_float2(acc[mt][nt][2], acc[mt][nt][3]);
        }
    }
}

// ---------------------------------------------------------------------------
// Kernel 4: reduce K-split partials + transpose to out[bc][o].
// ---------------------------------------------------------------------------
__global__ void qc_reduce(float* __restrict__ out) {
    __shared__ float sm[BC * 65];
    int t  = threadIdx.x;
    int o0 = blockIdx.x * 64;

    #pragma unroll
    for (int j = 0; j < 32; j++) {
        int idx = t + j * 256;                  // over 64*128
        int ol = idx >> 7, bc = idx & 127;
        float s = 0.f;
        #pragma unroll
        for (int kp = 0; kp < KSPLIT; kp++)
            s += g_part[(kp * NOUT + o0 + ol) * BC + bc];
        sm[bc * 65 + ol] = s;
    }
    __syncthreads();
    #pragma unroll
    for (int j = 0; j < 32; j++) {
        int idx = t + j * 256;
        int bc = idx >> 6, ol = idx & 63;
        out[bc * NOUT + o0 + ol] = sm[bc * 65 + ol];
    }
}

// ---------------------------------------------------------------------------
extern "C" void kernel_launch(void* const* d_in, const int* in_sizes, int n_in,
                              void* d_out, int out_size) {
    const float* features = (const float*)d_in[0];   // (4,32,4096) f32
    const float* G        = (const float*)d_in[1];   // (32,32)     f32
    const int*   idx_out  = (const int*)d_in[2];     // (E,) i32
    const int*   idx_in   = (const int*)d_in[3];     // (E,) i32
    float*       out      = (float*)d_out;           // (4,32,1024) f32
    int E = in_sizes[2];

    static const int GEMM_SMEM = 3 * 128 * ROWH * (int)sizeof(__half);  // 55296
    cudaFuncSetAttribute(qc_gemm_mma,
                         cudaFuncAttributeMaxDynamicSharedMemorySize, GEMM_SMEM);

    qc_prep<<<64, 256>>>(features, G);
    qc_count<<<(E + 255) / 256, 256>>>(idx_out, idx_in, E);
    qc_gemm_mma<<<MTILES * KSPLIT, 256, GEMM_SMEM>>>();
    qc_reduce<<<NOUT / 64, 256>>>(out);
}

// round 7
// speedup vs baseline: 1.8621x; 1.5329x over previous
#include <cuda_runtime.h>
#include <cuda_fp16.h>
#include <cstdint>

// ---------------- problem constants ----------------
#define NIN   4096
#define NOUT  1024
#define BC    128          // B*C = 4*32
#define C_DIM 32

// GEMM: D[o(1024), bc(128)] = sum_k M[o,k] * gftT[bc,k]
#define KSPLIT 16
#define KPB    (NIN / KSPLIT)   // 256
#define KC     64               // k per smem chunk
#define NCHUNK (KPB / KC)       // 4
#define MTILES (NOUT / 128)     // 8
#define ROWH   72               // smem row stride in halves (64 + 16B pad)

// ---------------- device scratch ----------------
__device__ float  g_Mf[NOUT * NIN];            // 16.8 MB count matrix (fp32)
__device__ __half g_ghi[BC * NIN];             // 1 MB  (G@F)^T hi (fp16)
__device__ __half g_glo[BC * NIN];             // 1 MB  (G@F)^T lo (fp16)

__device__ __forceinline__ uint32_t smem_u32(const void* p) {
    uint32_t a;
    asm("{ .reg .u64 t; cvta.to.shared.u64 t, %1; cvt.u32.u64 %0, t; }" : "=r"(a) : "l"(p));
    return a;
}

__device__ __forceinline__ void ldsm_x4(uint32_t* r, uint32_t addr) {
    asm volatile("ldmatrix.sync.aligned.m8n8.x4.shared.b16 {%0,%1,%2,%3}, [%4];"
                 : "=r"(r[0]), "=r"(r[1]), "=r"(r[2]), "=r"(r[3]) : "r"(addr));
}

__device__ __forceinline__ void mma16816(float* c, const uint32_t* a,
                                         uint32_t b0, uint32_t b1) {
    asm volatile(
        "mma.sync.aligned.m16n8k16.row.col.f32.f16.f16.f32 "
        "{%0,%1,%2,%3}, {%4,%5,%6,%7}, {%8,%9}, {%0,%1,%2,%3};"
        : "+f"(c[0]), "+f"(c[1]), "+f"(c[2]), "+f"(c[3])
        : "r"(a[0]), "r"(a[1]), "r"(a[2]), "r"(a[3]), "r"(b0), "r"(b1));
}

// ---------------------------------------------------------------------------
// Kernel 1: zero M + zero out + fused channel-GEMM producing gftT hi/lo.
// gftT[b*32+oc][n] = sum_i G[oc,i]*F[b,i,n].  Grid = 64 (4 b x 16 n-tiles).
// ---------------------------------------------------------------------------
__global__ void qc_prep(const float* __restrict__ F, const float* __restrict__ G,
                        float* __restrict__ out) {
    // zero count matrix: 1,048,576 float4 over 16384 threads
    float4* m4 = reinterpret_cast<float4*>(g_Mf);
    int gt = blockIdx.x * 256 + threadIdx.x;
    #pragma unroll
    for (int j = 0; j < 64; j++)
        m4[j * 16384 + gt] = make_float4(0.f, 0.f, 0.f, 0.f);
    // zero output (131072 floats = 32768 float4, 2 per thread)
    float4* o4 = reinterpret_cast<float4*>(out);
    o4[gt]         = make_float4(0.f, 0.f, 0.f, 0.f);
    o4[gt + 16384] = make_float4(0.f, 0.f, 0.f, 0.f);

    __shared__ float Fs[C_DIM * 256];
    __shared__ float Gs[C_DIM * 33];
    int t  = threadIdx.x;
    int b  = blockIdx.x >> 4;
    int n0 = (blockIdx.x & 15) * 256;

    #pragma unroll
    for (int j = 0; j < 32; j++) {
        int idx = t + j * 256;                       // idx = i*256 + nl
        Fs[idx] = F[b * (C_DIM * NIN) + (idx >> 8) * NIN + n0 + (idx & 255)];
    }
    #pragma unroll
    for (int j = 0; j < 4; j++) {
        int idx = t + j * 256;
        Gs[(idx >> 5) * 33 + (idx & 31)] = G[idx];
    }
    __syncthreads();

    #pragma unroll 4
    for (int oc = 0; oc < 32; oc++) {
        float s = 0.f;
        #pragma unroll
        for (int i = 0; i < 32; i++)
            s = fmaf(Gs[oc * 33 + i], Fs[i * 256 + t], s);
        __half h = __float2half_rn(s);
        __half l = __float2half_rn(s - __half2float(h));
        int row = b * 32 + oc;
        g_ghi[row * NIN + n0 + t] = h;
        g_glo[row * NIN + n0 + t] = l;
    }
}

// ---------------------------------------------------------------------------
// Kernel 2: build count matrix. Thread per edge, spread fp32 atomics.
// ---------------------------------------------------------------------------
__global__ void qc_count(const int* __restrict__ idx_out,
                         const int* __restrict__ idx_in, int E) {
    int e = blockIdx.x * blockDim.x + threadIdx.x;
    if (e >= E) return;
    atomicAdd(&g_Mf[idx_out[e] * NIN + idx_in[e]], 1.0f);
}

// ---------------------------------------------------------------------------
// Kernel 3: HMMA GEMM. Block = 256 threads (8 warps, 4x2), D tile 128o x 128bc,
// K range KPB=256 in 4 chunks of 64. A = M (fp32->fp16 on load), B = hi & lo,
// both accumulating into f32 fragments. Epilogue RED-adds straight into out
// (final bc-major layout); K-splits accumulate via L2 atomics (no partials).
// ---------------------------------------------------------------------------
__global__ void __launch_bounds__(256, 1) qc_gemm_mma(float* __restrict__ out) {
    extern __shared__ __half sm[];
    __half* As = sm;                 // 128 x ROWH
    __half* Bh = sm + 128 * ROWH;    // 128 x ROWH
    __half* Bl = sm + 256 * ROWH;    // 128 x ROWH

    int t    = threadIdx.x;
    int wid  = t >> 5;
    int lane = t & 31;
    int mt_b = blockIdx.x & 7;
    int ks   = blockIdx.x >> 3;
    int o0   = mt_b * 128;
    int k0   = ks * KPB;
    int wo   = (wid >> 1) * 32;      // warp o offset (0/32/64/96)
    int n0w  = (wid & 1) * 64;       // warp bc offset (0/64)

    uint32_t sA = smem_u32(As), sBh = smem_u32(Bh), sBl = smem_u32(Bl);

    float acc[2][8][4];
    #pragma unroll
    for (int i = 0; i < 2; i++)
        #pragma unroll
        for (int j = 0; j < 8; j++)
            #pragma unroll
            for (int q = 0; q < 4; q++) acc[i][j][q] = 0.f;

    for (int c = 0; c < NCHUNK; c++) {
        int kc0 = k0 + c * KC;

        // A tile: M[o0+row][kc0 + cp*2 ..] fp32 -> fp16 (coalesced 256B/warp)
        #pragma unroll
        for (int j = 0; j < 16; j++) {
            int idx = t + j * 256;          // 0..4095
            int row = idx >> 5, cp = idx & 31;
            float2 f2 = *reinterpret_cast<const float2*>(
                &g_Mf[(o0 + row) * NIN + kc0 + cp * 2]);
            *reinterpret_cast<__half2*>(&As[row * ROWH + cp * 2]) =
                __floats2half2_rn(f2.x, f2.y);
        }
        // B tiles hi/lo (uint32 = half2 moves, coalesced 128B/warp)
        #pragma unroll
        for (int j = 0; j < 16; j++) {
            int idx = t + j * 256;
            int row = idx >> 5, cp = idx & 31;
            int gsrc = row * NIN + kc0 + cp * 2;
            int sdst = row * ROWH + cp * 2;
            *reinterpret_cast<uint32_t*>(&Bh[sdst]) =
                *reinterpret_cast<const uint32_t*>(&g_ghi[gsrc]);
            *reinterpret_cast<uint32_t*>(&Bl[sdst]) =
                *reinterpret_cast<const uint32_t*>(&g_glo[gsrc]);
        }
        __syncthreads();

        #pragma unroll
        for (int kk = 0; kk < KC; kk += 16) {
            uint32_t a[2][4];
            #pragma unroll
            for (int mt = 0; mt < 2; mt++)
                ldsm_x4(a[mt], sA + 2 * ((wo + mt * 16 + (lane & 15)) * ROWH
                                          + kk + (lane >> 4) * 8));
            #pragma unroll
            for (int h = 0; h < 2; h++) {
                uint32_t sB = h ? sBl : sBh;
                #pragma unroll
                for (int ng = 0; ng < 4; ng++) {
                    uint32_t b[4];
                    ldsm_x4(b, sB + 2 * ((n0w + ng * 16 + (lane & 15)) * ROWH
                                          + kk + (lane >> 4) * 8));
                    #pragma unroll
                    for (int mt = 0; mt < 2; mt++) {
                        mma16816(acc[mt][ng * 2 + 0], a[mt], b[0], b[2]);
                        mma16816(acc[mt][ng * 2 + 1], a[mt], b[1], b[3]);
                    }
                }
            }
        }
        __syncthreads();
    }

    // Epilogue: RED straight into out[bc*NOUT + o] (zero-initialized by qc_prep).
    // Frag mapping: rows = lane>>2 (+8), cols = (lane&3)*2 + {0,1}.
    #pragma unroll
    for (int mt = 0; mt < 2; mt++) {
        #pragma unroll
        for (int nt = 0; nt < 8; nt++) {
            int o  = o0 + wo + mt * 16 + (lane >> 2);
            int bc = n0w + nt * 8 + (lane & 3) * 2;
            atomicAdd(&out[bc * NOUT + o],             acc[mt][nt][0]);
            atomicAdd(&out[(bc + 1) * NOUT + o],       acc[mt][nt][1]);
            atomicAdd(&out[bc * NOUT + o + 8],         acc[mt][nt][2]);
            atomicAdd(&out[(bc + 1) * NOUT + o + 8],   acc[mt][nt][3]);
        }
    }
}

// ---------------------------------------------------------------------------
extern "C" void kernel_launch(void* const* d_in, const int* in_sizes, int n_in,
                              void* d_out, int out_size) {
    const float* features = (const float*)d_in[0];   // (4,32,4096) f32
    const float* G        = (const float*)d_in[1];   // (32,32)     f32
    const int*   idx_out  = (const int*)d_in[2];     // (E,) i32
    const int*   idx_in   = (const int*)d_in[3];     // (E,) i32
    float*       out      = (float*)d_out;           // (4,32,1024) f32
    int E = in_sizes[2];

    static const int GEMM_SMEM = 3 * 128 * ROWH * (int)sizeof(__half);  // 55296
    cudaFuncSetAttribute(qc_gemm_mma,
                         cudaFuncAttributeMaxDynamicSharedMemorySize, GEMM_SMEM);

    qc_prep<<<64, 256>>>(features, G, out);
    qc_count<<<(E + 255) / 256, 256>>>(idx_out, idx_in, E);
    qc_gemm_mma<<<MTILES * KSPLIT, 256, GEMM_SMEM>>>(out);
}